// round 15
// baseline (speedup 1.0000x reference)
#include <cuda_runtime.h>
#include <cuda_bf16.h>
#include <cstdint>

// HartleySpectralConv2d B=16,CI=CO=64,H=W=256, modes 64x64.
// Split-bf16 HMMA. R15 = R13 base + (a) k12 K1 merged to single N=256 pass,
// (b) g_Ttp transposed to [tpos][img] for coalesced k_mix stores.

using bf16 = __nv_bfloat16;
using u32 = uint32_t; using ull = unsigned long long;

__device__ bf16 g_Tch[128 * 256], g_Tcl[128 * 256];       // [j][a] K-major
__device__ bf16 g_A5h[2 * 256 * 64], g_A5l[2 * 256 * 64]; // [(c*256+m)][s1]
__device__ bf16 g_T5h[256 * 128], g_T5l[256 * 128];       // [n][c*64+s2]
__device__ bf16 g_Wth[4096 * 4096], g_Wtl[4096 * 4096];   // [mode][o*64+i] split
__device__ float g_CS[2 * 4096 * 1024];                   // [comp][mode][ci*16+b]
__device__ u32 g_Ttp[4096 * 1024];                        // [tpos][img] packed(h,l)

// ---------------- helpers ----------------
__device__ __forceinline__ u32 smem_u32(const void* p) {
    u32 a;
    asm("{ .reg .u64 t; cvta.to.shared.u64 t, %1; cvt.u32.u64 %0, t; }" : "=r"(a) : "l"(p));
    return a;
}
__device__ __forceinline__ void ldsm4(u32* r, u32 a) {
    asm volatile("ldmatrix.sync.aligned.m8n8.x4.shared.b16 {%0,%1,%2,%3}, [%4];"
                 : "=r"(r[0]), "=r"(r[1]), "=r"(r[2]), "=r"(r[3]) : "r"(a));
}
__device__ __forceinline__ void ldsm2(u32* r, u32 a) {
    asm volatile("ldmatrix.sync.aligned.m8n8.x2.shared.b16 {%0,%1}, [%2];"
                 : "=r"(r[0]), "=r"(r[1]) : "r"(a));
}
__device__ __forceinline__ void mmabf(float* d, const u32* a, const u32* b) {
    asm volatile("mma.sync.aligned.m16n8k16.row.col.f32.bf16.bf16.f32 "
                 "{%0,%1,%2,%3}, {%4,%5,%6,%7}, {%8,%9}, {%0,%1,%2,%3};"
                 : "+f"(d[0]), "+f"(d[1]), "+f"(d[2]), "+f"(d[3])
                 : "r"(a[0]), "r"(a[1]), "r"(a[2]), "r"(a[3]), "r"(b[0]), "r"(b[1]));
}
__device__ __forceinline__ void cpa(u32 s, const void* g) {
    asm volatile("cp.async.cg.shared.global [%0], [%1], 16;" :: "r"(s), "l"(g));
}
#define CPC()  asm volatile("cp.async.commit_group;" ::: "memory")
#define CPW1() asm volatile("cp.async.wait_group 1;" ::: "memory")
#define CPW0() asm volatile("cp.async.wait_group 0;" ::: "memory")

__device__ __forceinline__ u32 pack_bf(bf16 a, bf16 b) {
    return (u32)__bfloat16_as_ushort(a) | ((u32)__bfloat16_as_ushort(b) << 16);
}
__device__ __forceinline__ void bsplit(float v, bf16& h, bf16& l) {
    h = __float2bfloat16(v);
    l = __float2bfloat16(v - __bfloat162float(h));
}
__device__ __forceinline__ u32 pack_h(float a, float b) {
    bf16 h0, l0, h1, l1; bsplit(a, h0, l0); bsplit(b, h1, l1); return pack_bf(h0, h1);
}
__device__ __forceinline__ u32 pack_l(float a, float b) {
    bf16 h0, l0, h1, l1; bsplit(a, h0, l0); bsplit(b, h1, l1); return pack_bf(l0, l1);
}

// swizzles (conflict-free for 8-row ldsm phases)
__device__ __forceinline__ u32 SWZ(int row, int c) {           // 64B rows
    return (u32)(row * 64 + ((c ^ ((row >> 1) & 3)) << 4));
}
__device__ __forceinline__ u32 swzU(int j, int c16) {          // 512B rows
    return (u32)(j * 512 + ((((c16 ^ j) & 7) | (c16 & 24)) << 4));
}
__device__ __forceinline__ u32 swzW(int m, int c16) {          // 256B rows
    return (u32)(m * 256 + ((((c16 ^ m) & 7) | (c16 & 8)) << 4));
}
__device__ __forceinline__ u32 swzT(int r, int c16) {          // 128B rows
    return (u32)(r * 128 + ((c16 ^ (r & 7)) << 4));
}

// ---------------- K0: split trig tables ----------------
__global__ void k_tables() {
    int a = blockIdx.x, b = threadIdx.x;
    int s = b & 63, k = s - 32;
    int q = ((k * a) % 256 + 256) % 256;
    float sv, cv;
    sincospif((float)q * (1.0f / 128.0f), &sv, &cv);
    float tc = (b < 64) ? cv : sv;
    bf16 h, l;
    bsplit(tc, h, l);
    g_Tch[b * 256 + a] = h; g_Tcl[b * 256 + a] = l;
    g_T5h[a * 128 + b] = h; g_T5l[a * 128 + b] = l;
    int c = b >> 6;
    float a5 = c ? (cv - sv) : (cv + sv);
    bsplit(a5, h, l);
    g_A5h[(c * 256 + a) * 64 + s] = h;
    g_A5l[(c * 256 + a) * 64 + s] = l;
}

// ---------------- Kw: weight transpose + split ----------------
__global__ __launch_bounds__(256) void k_wt(const float* __restrict__ w) {
    __shared__ float tile[64][65];
    int bx = blockIdx.x, o = blockIdx.y;
    int tid = threadIdx.x;
    int tx = tid & 63, tg = tid >> 6;
#pragma unroll
    for (int it = 0; it < 16; it++) {
        int i = tg + it * 4;
        tile[i][tx] = w[(size_t)(i * 64 + o) * 4096 + bx * 64 + tx];
    }
    __syncthreads();
#pragma unroll
    for (int it = 0; it < 16; it++) {
        int xy = tg + it * 4;
        float v = tile[tx][xy];
        bf16 h, l;
        bsplit(v, h, l);
        size_t dst = (size_t)(bx * 64 + xy) * 4096 + o * 64 + tx;
        g_Wth[dst] = h;
        g_Wtl[dst] = l;
    }
}

// ---------------- K12: fused forward (per image) ----------------
// smem: Ut_h @0 (64K), Ut_l @65536 (64K), pipeline @131072.
// K1 stage (2x): Ah@0(8K) Al@8192 Bh@16384(16K) Bl@32768 -> 49152 each.
// K2 stage (3x16K) fits in same region.
__global__ __launch_bounds__(512, 1) void k12(const float* __restrict__ x) {
    extern __shared__ char smem[];
    u32 sb = smem_u32(smem);
    const int PIPE = 131072, STG1 = 49152;
    int tid = threadIdx.x, lane = tid & 31, w = tid >> 5;
    int wy = w >> 2, wx = w & 3;        // 4x4 warp grid
    int img = blockIdx.x;
    int g = lane >> 2, cp2 = (lane & 3) * 2;
    int rA = wy * 32 + (lane & 15), cA = lane >> 4;
    int rB2 = wx * 32 + (lane & 7) + ((lane >> 4) << 3);   // K2 B (N=128)
    int rB1 = wx * 64 + (lane & 7) + ((lane >> 4) << 3);   // K1 B (N=256)
    int cB = (lane >> 3) & 1;

    // ======== K1: single pass, M=128(j) x N=256(m), K=256 ========
    {
        const float* xb = x + (size_t)img * 65536;
        float c[2][8][4];
#pragma unroll
        for (int i = 0; i < 2; i++)
#pragma unroll
            for (int j = 0; j < 8; j++)
#pragma unroll
                for (int r = 0; r < 4; r++) c[i][j][r] = 0.f;
        // prologue: stages 0,1
#pragma unroll
        for (int st = 0; st < 2; st++) {
            u32 b = sb + PIPE + st * STG1;
            { int row = tid >> 2, q = tid & 3;   // A: 128 rows x 4 = 512 exact
              cpa(b + SWZ(row, q), &g_Tch[row * 256 + st * 32 + q * 8]);
              cpa(b + 8192 + SWZ(row, q), &g_Tcl[row * 256 + st * 32 + q * 8]); }
            CPC();
#pragma unroll
            for (int t = 0; t < 2; t++) {        // B(x): 256 rows x 4 = 1024 slots
                int f = tid + t * 512;
                int row = f >> 2, q = f & 3;
                const float* s = &xb[row * 256 + st * 32 + q * 8];
                float4 v0 = *(const float4*)s, v1 = *(const float4*)(s + 4);
                u32 h4[4] = {pack_h(v0.x, v0.y), pack_h(v0.z, v0.w), pack_h(v1.x, v1.y), pack_h(v1.z, v1.w)};
                u32 l4[4] = {pack_l(v0.x, v0.y), pack_l(v0.z, v0.w), pack_l(v1.x, v1.y), pack_l(v1.z, v1.w)};
                *(uint4*)(smem + PIPE + st * STG1 + 16384 + SWZ(row, q)) = *(uint4*)h4;
                *(uint4*)(smem + PIPE + st * STG1 + 32768 + SWZ(row, q)) = *(uint4*)l4;
            }
        }
        const int NCH = 8;
        for (int ch = 0; ch < NCH; ch++) {
            if (ch + 1 < NCH) { CPW1(); } else { CPW0(); }
            __syncthreads();
            bool pre = (ch + 2 < NCH);
            float4 pv[2][2];
            if (pre) {
#pragma unroll
                for (int t = 0; t < 2; t++) {
                    int f = tid + t * 512;
                    int row = f >> 2, q = f & 3;
                    const float* s = &xb[row * 256 + (ch + 2) * 32 + q * 8];
                    pv[t][0] = *(const float4*)s;       // LDG early
                    pv[t][1] = *(const float4*)(s + 4);
                }
            }
            u32 base = sb + PIPE + (ch & 1) * STG1;
#pragma unroll
            for (int kk = 0; kk < 2; kk++) {
                int kc = kk * 2;
                u32 ah[2][4], al[2][4], bh[4][4], bl[4][4];
#pragma unroll
                for (int mi = 0; mi < 2; mi++) {
                    u32 ao = SWZ(rA + mi * 16, kc + cA);
                    ldsm4(ah[mi], base + ao);
                    ldsm4(al[mi], base + 8192 + ao);
                }
#pragma unroll
                for (int np = 0; np < 4; np++) {
                    u32 bo = SWZ(rB1 + np * 16, kc + cB);
                    ldsm4(bh[np], base + 16384 + bo);
                    ldsm4(bl[np], base + 32768 + bo);
                }
#pragma unroll
                for (int mi = 0; mi < 2; mi++)
#pragma unroll
                    for (int ni = 0; ni < 8; ni++)
                        mmabf(c[mi][ni], ah[mi], &bh[ni >> 1][(ni & 1) * 2]);
#pragma unroll
                for (int mi = 0; mi < 2; mi++)
#pragma unroll
                    for (int ni = 0; ni < 8; ni++)
                        mmabf(c[mi][ni], ah[mi], &bl[ni >> 1][(ni & 1) * 2]);
#pragma unroll
                for (int mi = 0; mi < 2; mi++)
#pragma unroll
                    for (int ni = 0; ni < 8; ni++)
                        mmabf(c[mi][ni], al[mi], &bh[ni >> 1][(ni & 1) * 2]);
            }
            if (pre) {
                __syncthreads();   // all warps done with buffer (ch&1)
                u32 o = PIPE + (ch & 1) * STG1;
#pragma unroll
                for (int t = 0; t < 2; t++) {
                    int f = tid + t * 512;
                    int row = f >> 2, q = f & 3;
                    float4 v0 = pv[t][0], v1 = pv[t][1];
                    u32 h4[4] = {pack_h(v0.x, v0.y), pack_h(v0.z, v0.w), pack_h(v1.x, v1.y), pack_h(v1.z, v1.w)};
                    u32 l4[4] = {pack_l(v0.x, v0.y), pack_l(v0.z, v0.w), pack_l(v1.x, v1.y), pack_l(v1.z, v1.w)};
                    *(uint4*)(smem + o + 16384 + SWZ(row, q)) = *(uint4*)h4;
                    *(uint4*)(smem + o + 32768 + SWZ(row, q)) = *(uint4*)l4;
                }
                { int row = tid >> 2, q = tid & 3;
                  cpa(sb + o + SWZ(row, q), &g_Tch[row * 256 + (ch + 2) * 32 + q * 8]);
                  cpa(sb + o + 8192 + SWZ(row, q), &g_Tcl[row * 256 + (ch + 2) * 32 + q * 8]); }
                CPC();
            }
        }
        // epilogue: write Ut smem (h/l, swizzled) — full m range in one pass
#pragma unroll
        for (int mi = 0; mi < 2; mi++)
#pragma unroll
            for (int ni = 0; ni < 8; ni++) {
                int m = wx * 64 + ni * 8 + cp2;
                int j0 = wy * 32 + mi * 16 + g;
                float* d = c[mi][ni];
                u32 a0 = swzU(j0, m >> 3) + (m & 7) * 2;
                u32 a1 = swzU(j0 + 8, m >> 3) + (m & 7) * 2;
                *(u32*)(smem + a0) = pack_h(d[0], d[1]);
                *(u32*)(smem + 65536 + a0) = pack_l(d[0], d[1]);
                *(u32*)(smem + a1) = pack_h(d[2], d[3]);
                *(u32*)(smem + 65536 + a1) = pack_l(d[2], d[3]);
            }
        __syncthreads();
    }

    // ======== K2: B from smem Ut ========
    {
        const int xrow = tid >> 2, xq = tid & 3;
        float c[2][4][4];
#pragma unroll
        for (int i = 0; i < 2; i++)
#pragma unroll
            for (int j = 0; j < 4; j++)
#pragma unroll
                for (int r = 0; r < 4; r++) c[i][j][r] = 0.f;
#pragma unroll
        for (int st = 0; st < 2; st++) {
            u32 b = sb + PIPE + st * 16384;
            cpa(b + SWZ(xrow, xq), &g_Tch[xrow * 256 + st * 32 + xq * 8]);
            cpa(b + 8192 + SWZ(xrow, xq), &g_Tcl[xrow * 256 + st * 32 + xq * 8]);
            CPC();
        }
        const int NCH = 8;
        for (int ch = 0; ch < NCH; ch++) {
            if (ch + 1 < NCH) { CPW1(); } else { CPW0(); }
            __syncthreads();
            if (ch + 2 < NCH) {
                u32 b = sb + PIPE + ((ch + 2) % 3) * 16384;
                cpa(b + SWZ(xrow, xq), &g_Tch[xrow * 256 + (ch + 2) * 32 + xq * 8]);
                cpa(b + 8192 + SWZ(xrow, xq), &g_Tcl[xrow * 256 + (ch + 2) * 32 + xq * 8]);
                CPC();
            }
            u32 base = sb + PIPE + (ch % 3) * 16384;
#pragma unroll
            for (int kk = 0; kk < 2; kk++) {
                u32 ah[2][4], al[2][4], bh[2][4], bl[2][4];
#pragma unroll
                for (int mi = 0; mi < 2; mi++) {
                    u32 ao = SWZ(rA + mi * 16, kk * 2 + cA);
                    ldsm4(ah[mi], base + ao);
                    ldsm4(al[mi], base + 8192 + ao);
                }
#pragma unroll
                for (int np = 0; np < 2; np++) {
                    int c16 = ch * 4 + kk * 2 + cB;
                    u32 bo = swzU(rB2 + np * 16, c16);
                    ldsm4(bh[np], sb + bo);
                    ldsm4(bl[np], sb + 65536 + bo);
                }
#pragma unroll
                for (int mi = 0; mi < 2; mi++)
#pragma unroll
                    for (int ni = 0; ni < 4; ni++)
                        mmabf(c[mi][ni], ah[mi], &bh[ni >> 1][(ni & 1) * 2]);
#pragma unroll
                for (int mi = 0; mi < 2; mi++)
#pragma unroll
                    for (int ni = 0; ni < 4; ni++)
                        mmabf(c[mi][ni], ah[mi], &bl[ni >> 1][(ni & 1) * 2]);
#pragma unroll
                for (int mi = 0; mi < 2; mi++)
#pragma unroll
                    for (int ni = 0; ni < 4; ni++)
                        mmabf(c[mi][ni], al[mi], &bh[ni >> 1][(ni & 1) * 2]);
            }
        }
        __syncthreads();
        float* F = (float*)(smem + PIPE);
#pragma unroll
        for (int mi = 0; mi < 2; mi++)
#pragma unroll
            for (int ni = 0; ni < 4; ni++) {
                int col = wx * 32 + ni * 8 + cp2;
                int r0 = wy * 32 + mi * 16 + g;
                float* d = c[mi][ni];
                F[r0 * 132 + col] = d[0];
                F[r0 * 132 + col + 1] = d[1];
                F[(r0 + 8) * 132 + col] = d[2];
                F[(r0 + 8) * 132 + col + 1] = d[3];
            }
        __syncthreads();
        const int b = img >> 6, ic = img & 63;
#pragma unroll
        for (int t = 0; t < 8; t++) {
            int p = tid + t * 512;
            int s1 = p >> 6, s2 = p & 63;
            float r00 = F[s1 * 132 + s2];
            float r01 = F[s1 * 132 + 64 + s2];
            float r10 = F[(64 + s1) * 132 + s2];
            float r11 = F[(64 + s1) * 132 + 64 + s2];
            int a = p * 1024 + ic * 16 + b;
            g_CS[a] = r00 - r11;
            g_CS[4194304 + a] = r10 + r01;
        }
    }
}

// ---------------- K3: paired channel mixing (split-bf16 HMMA) ----------------
__global__ __launch_bounds__(256) void k_mix() {
    __shared__ __align__(16) char sm[49152];
    u32 sb = smem_u32(sm);
    const int m0 = blockIdx.x;
    const int s1 = m0 >> 6, s2 = m0 & 63;
    const int f1 = (64 - s1) & 63, f2 = (64 - s2) & 63;
    const int f0 = f1 * 64 + f2;
    if (m0 > f0) return;
    const bool dual = (f0 != m0);
    const int tid = threadIdx.x, lane = tid & 31, w = tid >> 5;
#pragma unroll
    for (int t = 0; t < 2; t++) {
        int f = tid + t * 256;
        int o = f >> 3, c16 = f & 7;
        size_t src = (size_t)m0 * 4096 + o * 64 + c16 * 8;
        size_t srcf = (size_t)f0 * 4096 + o * 64 + c16 * 8;
        cpa(sb + 16384 + swzT(o, c16), &g_Wth[src]);
        cpa(sb + 24576 + swzT(o, c16), &g_Wtl[src]);
        cpa(sb + 32768 + swzT(o, c16), &g_Wth[srcf]);
        cpa(sb + 40960 + swzT(o, c16), &g_Wtl[srcf]);
    }
    CPC();
    {
        float4 cv = *(const float4*)&g_CS[m0 * 1024 + tid * 4];
        float4 sv = *(const float4*)&g_CS[4194304 + m0 * 1024 + tid * 4];
        float cva[4] = {cv.x, cv.y, cv.z, cv.w}, sva[4] = {sv.x, sv.y, sv.z, sv.w};
#pragma unroll
        for (int q = 0; q < 4; q++) {
            int j = tid * 4 + q;
            int b = j & 15, ci = j >> 4;
            u32 a = swzT(b, ci >> 3) + (ci & 7) * 2;
            bf16 h, l;
            bsplit(cva[q], h, l);
            *(unsigned short*)(sm + a) = __bfloat16_as_ushort(h);
            *(unsigned short*)(sm + 2048 + a) = __bfloat16_as_ushort(l);
            bsplit(sva[q], h, l);
            *(unsigned short*)(sm + 4096 + a) = __bfloat16_as_ushort(h);
            *(unsigned short*)(sm + 6144 + a) = __bfloat16_as_ushort(l);
        }
        if (dual) {
            float4 cvf = *(const float4*)&g_CS[f0 * 1024 + tid * 4];
            float4 svf = *(const float4*)&g_CS[4194304 + f0 * 1024 + tid * 4];
            float cvb[4] = {cvf.x, cvf.y, cvf.z, cvf.w}, svb[4] = {svf.x, svf.y, svf.z, svf.w};
#pragma unroll
            for (int q = 0; q < 4; q++) {
                int j = tid * 4 + q;
                int b = j & 15, ci = j >> 4;
                u32 a = swzT(b, ci >> 3) + (ci & 7) * 2;
                bf16 h, l;
                bsplit(cvb[q], h, l);
                *(unsigned short*)(sm + 8192 + a) = __bfloat16_as_ushort(h);
                *(unsigned short*)(sm + 10240 + a) = __bfloat16_as_ushort(l);
                bsplit(svb[q], h, l);
                *(unsigned short*)(sm + 12288 + a) = __bfloat16_as_ushort(h);
                *(unsigned short*)(sm + 14336 + a) = __bfloat16_as_ushort(l);
            }
        }
    }
    CPW0();
    __syncthreads();
    float acc0[4] = {0.f, 0.f, 0.f, 0.f};
    float acc1[4] = {0.f, 0.f, 0.f, 0.f};
    const int o0 = w * 8;
    const int arow = lane & 15, ac = lane >> 4;
    const int brow = o0 + (lane & 7), bc = (lane >> 3) & 1;
#pragma unroll
    for (int kc = 0; kc < 4; kc++) {
        u32 ao = swzT(arow, kc * 2 + ac);
        u32 bo = swzT(brow, kc * 2 + bc);
        u32 bh[2], bl[2], brh[2], brl[2];
        ldsm2(bh, sb + 16384 + bo);
        ldsm2(bl, sb + 24576 + bo);
        ldsm2(brh, sb + 32768 + bo);
        ldsm2(brl, sb + 40960 + bo);
        {
            u32 ach[4], acl[4], ash[4], asl[4];
            ldsm4(ach, sb + ao);
            ldsm4(acl, sb + 2048 + ao);
            ldsm4(ash, sb + 4096 + ao);
            ldsm4(asl, sb + 6144 + ao);
            mmabf(acc0, ach, bh);
            mmabf(acc0, ach, bl);
            mmabf(acc0, acl, bh);
            mmabf(acc0, ash, brh);
            mmabf(acc0, ash, brl);
            mmabf(acc0, asl, brh);
        }
        if (dual) {
            u32 ach[4], acl[4], ash[4], asl[4];
            ldsm4(ach, sb + 8192 + ao);
            ldsm4(acl, sb + 10240 + ao);
            ldsm4(ash, sb + 12288 + ao);
            ldsm4(asl, sb + 14336 + ao);
            mmabf(acc1, ach, brh);
            mmabf(acc1, ach, brl);
            mmabf(acc1, acl, brh);
            mmabf(acc1, ash, bh);
            mmabf(acc1, ash, bl);
            mmabf(acc1, asl, bh);
        }
    }
    // epilogue: coalesced stores to [tpos][img]
    const int g = lane >> 2, cp2 = (lane & 3) * 2;
    const int tpos0 = s2 * 64 + s1;
    const int tpos1 = f2 * 64 + f1;
#pragma unroll
    for (int half = 0; half < 2; half++) {
        int b = g + half * 8;
        bf16 h, l;
        bsplit(acc0[half * 2], h, l);
        g_Ttp[(size_t)tpos0 * 1024 + b * 64 + o0 + cp2] = pack_bf(h, l);
        bsplit(acc0[half * 2 + 1], h, l);
        g_Ttp[(size_t)tpos0 * 1024 + b * 64 + o0 + cp2 + 1] = pack_bf(h, l);
        if (dual) {
            bsplit(acc1[half * 2], h, l);
            g_Ttp[(size_t)tpos1 * 1024 + b * 64 + o0 + cp2] = pack_bf(h, l);
            bsplit(acc1[half * 2 + 1], h, l);
            g_Ttp[(size_t)tpos1 * 1024 + b * 64 + o0 + cp2 + 1] = pack_bf(h, l);
        }
    }
}

// ---------------- K45: fused inverse (per image) ----------------
__global__ __launch_bounds__(512, 1) void k45(const float* __restrict__ bias,
                                              float* __restrict__ out) {
    extern __shared__ char smem[];
    u32 sb = smem_u32(smem);
    const int PIPE = 131072, TT = 196608;
    int tid = threadIdx.x, lane = tid & 31, w = tid >> 5;
    int wy = w >> 1, wx = w & 1;
    int img = blockIdx.x;
    int g = lane >> 2, cp2 = (lane & 3) * 2;

    auto issueA = [&](int slot) {
        int cc = slot >> 1, k0 = (slot & 1) * 32;
        const bf16* Ah = g_A5h + cc * 16384;
        const bf16* Al = g_A5l + cc * 16384;
        u32 b = sb + PIPE + (slot & 1) * 32768;
#pragma unroll
        for (int t = 0; t < 2; t++) {
            int f = tid + t * 512, row = f >> 2, q = f & 3;
            cpa(b + SWZ(row, q), &Ah[row * 64 + k0 + q * 8]);
            cpa(b + 16384 + SWZ(row, q), &Al[row * 64 + k0 + q * 8]);
        }
        CPC();
    };
    issueA(0); issueA(1);

    // unpack packed Tot (gather [tpos][img], L2-resident) into h/l tiles
#pragma unroll
    for (int t = 0; t < 8; t++) {
        int p = tid + t * 512;
        u32 v = g_Ttp[(size_t)p * 1024 + img];
        int r = p >> 6, cc = p & 63;
        u32 a = swzT(r, cc >> 3) + (cc & 7) * 2;
        *(unsigned short*)(smem + TT + a) = (unsigned short)(v & 0xFFFF);
        *(unsigned short*)(smem + TT + 8192 + a) = (unsigned short)(v >> 16);
    }

    int rA = wy * 32 + (lane & 15), cA = lane >> 4;
    int rB = wx * 32 + (lane & 7) + ((lane >> 4) << 3), cB = (lane >> 3) & 1;
    for (int cpass = 0; cpass < 2; cpass++) {
        float acc[2][4][4];
#pragma unroll
        for (int i = 0; i < 2; i++)
#pragma unroll
            for (int j = 0; j < 4; j++)
#pragma unroll
                for (int r = 0; r < 4; r++) acc[i][j][r] = 0.f;
        for (int k = 0; k < 2; k++) {
            int slot = cpass * 2 + k;
            if (slot < 3) { CPW1(); } else { CPW0(); }
            __syncthreads();
            u32 stg = sb + PIPE + (slot & 1) * 32768;
#pragma unroll
            for (int kk = 0; kk < 2; kk++) {
                u32 ah[2][4], al[2][4], bh[2][4], bl[2][4];
#pragma unroll
                for (int mi = 0; mi < 2; mi++) {
                    u32 ao = SWZ(rA + mi * 16, kk * 2 + cA);
                    ldsm4(ah[mi], stg + ao);
                    ldsm4(al[mi], stg + 16384 + ao);
                }
#pragma unroll
                for (int np = 0; np < 2; np++) {
                    int c16 = k * 4 + kk * 2 + cB;
                    u32 bo = swzT(rB + np * 16, c16);
                    ldsm4(bh[np], sb + TT + bo);
                    ldsm4(bl[np], sb + TT + 8192 + bo);
                }
#pragma unroll
                for (int mi = 0; mi < 2; mi++)
#pragma unroll
                    for (int ni = 0; ni < 4; ni++)
                        mmabf(acc[mi][ni], ah[mi], &bh[ni >> 1][(ni & 1) * 2]);
#pragma unroll
                for (int mi = 0; mi < 2; mi++)
#pragma unroll
                    for (int ni = 0; ni < 4; ni++)
                        mmabf(acc[mi][ni], ah[mi], &bl[ni >> 1][(ni & 1) * 2]);
#pragma unroll
                for (int mi = 0; mi < 2; mi++)
#pragma unroll
                    for (int ni = 0; ni < 4; ni++)
                        mmabf(acc[mi][ni], al[mi], &bh[ni >> 1][(ni & 1) * 2]);
            }
            __syncthreads();
            if (slot + 2 < 4) issueA(slot + 2);
        }
#pragma unroll
        for (int mi = 0; mi < 2; mi++)
#pragma unroll
            for (int ni = 0; ni < 4; ni++) {
                int col = cpass * 64 + wx * 32 + ni * 8 + cp2;
                int m0 = wy * 32 + mi * 16 + g;
                float* d = acc[mi][ni];
                u32 a0 = swzW(m0, col >> 3) + (col & 7) * 2;
                u32 a1 = swzW(m0 + 8, col >> 3) + (col & 7) * 2;
                *(u32*)(smem + a0) = pack_h(d[0], d[1]);
                *(u32*)(smem + 65536 + a0) = pack_l(d[0], d[1]);
                *(u32*)(smem + a1) = pack_h(d[2], d[3]);
                *(u32*)(smem + 65536 + a1) = pack_l(d[2], d[3]);
            }
    }
    __syncthreads();

    const float bv = bias[img & 63];
    const float sc = 1.0f / 65536.0f;
    int rB5 = wx * 64 + (lane & 7) + ((lane >> 4) << 3);
    for (int nh = 0; nh < 2; nh++) {
        float c5[2][8][4];
#pragma unroll
        for (int i = 0; i < 2; i++)
#pragma unroll
            for (int j = 0; j < 8; j++)
#pragma unroll
                for (int r = 0; r < 4; r++) c5[i][j][r] = 0.f;
        int xrow = tid >> 2, xq = tid & 3;
#pragma unroll
        for (int st = 0; st < 2; st++) {
            u32 b = sb + PIPE + st * 16384;
            cpa(b + SWZ(xrow, xq), &g_T5h[(nh * 128 + xrow) * 128 + st * 32 + xq * 8]);
            cpa(b + 8192 + SWZ(xrow, xq), &g_T5l[(nh * 128 + xrow) * 128 + st * 32 + xq * 8]);
            CPC();
        }
        for (int ch = 0; ch < 4; ch++) {
            if (ch < 3) { CPW1(); } else { CPW0(); }
            __syncthreads();
            if (ch + 2 < 4) {
                u32 b = sb + PIPE + ((ch + 2) % 3) * 16384;
                cpa(b + SWZ(xrow, xq), &g_T5h[(nh * 128 + xrow) * 128 + (ch + 2) * 32 + xq * 8]);
                cpa(b + 8192 + SWZ(xrow, xq), &g_T5l[(nh * 128 + xrow) * 128 + (ch + 2) * 32 + xq * 8]);
                CPC();
            }
            u32 stg = sb + PIPE + (ch % 3) * 16384;
#pragma unroll
            for (int kk = 0; kk < 2; kk++) {
                u32 ah[2][4], al[2][4], bh[4][4], bl[4][4];
#pragma unroll
                for (int mi = 0; mi < 2; mi++) {
                    int c16 = ch * 4 + kk * 2 + cA;
                    u32 ao = swzW(rA + mi * 16, c16);
                    ldsm4(ah[mi], sb + ao);
                    ldsm4(al[mi], sb + 65536 + ao);
                }
#pragma unroll
                for (int np = 0; np < 4; np++) {
                    u32 bo = SWZ(rB5 + np * 16, kk * 2 + cB);
                    ldsm4(bh[np], stg + bo);
                    ldsm4(bl[np], stg + 8192 + bo);
                }
#pragma unroll
                for (int mi = 0; mi < 2; mi++)
#pragma unroll
                    for (int ni = 0; ni < 8; ni++)
                        mmabf(c5[mi][ni], ah[mi], &bh[ni >> 1][(ni & 1) * 2]);
#pragma unroll
                for (int mi = 0; mi < 2; mi++)
#pragma unroll
                    for (int ni = 0; ni < 8; ni++)
                        mmabf(c5[mi][ni], ah[mi], &bl[ni >> 1][(ni & 1) * 2]);
#pragma unroll
                for (int mi = 0; mi < 2; mi++)
#pragma unroll
                    for (int ni = 0; ni < 8; ni++)
                        mmabf(c5[mi][ni], al[mi], &bh[ni >> 1][(ni & 1) * 2]);
            }
        }
#pragma unroll
        for (int mi = 0; mi < 2; mi++)
#pragma unroll
            for (int ni = 0; ni < 8; ni++) {
                int col = nh * 128 + wx * 64 + ni * 8 + cp2;
                float* d = c5[mi][ni];
#pragma unroll
                for (int half = 0; half < 2; half++) {
                    int m = wy * 32 + mi * 16 + g + half * 8;
                    float2 v;
                    v.x = fmaxf(fmaf(d[half * 2], sc, bv), 0.f);
                    v.y = fmaxf(fmaf(d[half * 2 + 1], sc, bv), 0.f);
                    *(float2*)&out[(size_t)img * 65536 + m * 256 + col] = v;
                }
            }
        __syncthreads();
    }
}

extern "C" void kernel_launch(void* const* d_in, const int* in_sizes, int n_in,
                              void* d_out, int out_size) {
    const float* x = (const float*)d_in[0];
    const float* wgt = (const float*)d_in[1];
    const float* bias = (const float*)d_in[2];
    float* out = (float*)d_out;

    static cudaStream_t side = nullptr;
    static cudaEvent_t evFork = nullptr, evJoin = nullptr;
    if (!side) {
        cudaStreamCreateWithFlags(&side, cudaStreamNonBlocking);
        cudaEventCreateWithFlags(&evFork, cudaEventDisableTiming);
        cudaEventCreateWithFlags(&evJoin, cudaEventDisableTiming);
    }
    cudaFuncSetAttribute(k12, cudaFuncAttributeMaxDynamicSharedMemorySize, 229376);
    cudaFuncSetAttribute(k45, cudaFuncAttributeMaxDynamicSharedMemorySize, 212992);

    cudaEventRecord(evFork, 0);
    cudaStreamWaitEvent(side, evFork, 0);
    k_wt<<<dim3(64, 64), 256, 0, side>>>(wgt);
    cudaEventRecord(evJoin, side);

    k_tables<<<256, 128>>>();
    k12<<<1024, 512, 229376>>>(x);

    cudaStreamWaitEvent(0, evJoin, 0);
    k_mix<<<4096, 256>>>();
    k45<<<1024, 512, 212992>>>(bias, out);
}

// round 16
// speedup vs baseline: 1.1021x; 1.1021x over previous
#include <cuda_runtime.h>
#include <cuda_bf16.h>
#include <cstdint>

// HartleySpectralConv2d B=16,CI=CO=64,H=W=256, modes 64x64.
// Split-bf16 HMMA. R16 = R13's k12 (proven) + R15's transposed g_Ttp
// (coalesced k_mix stores, L2-gather unpack in k45).

using bf16 = __nv_bfloat16;
using u32 = uint32_t; using ull = unsigned long long;

__device__ bf16 g_Tch[128 * 256], g_Tcl[128 * 256];       // [j][a] K-major
__device__ bf16 g_A5h[2 * 256 * 64], g_A5l[2 * 256 * 64]; // [(c*256+m)][s1]
__device__ bf16 g_T5h[256 * 128], g_T5l[256 * 128];       // [n][c*64+s2]
__device__ bf16 g_Wth[4096 * 4096], g_Wtl[4096 * 4096];   // [mode][o*64+i] split
__device__ float g_CS[2 * 4096 * 1024];                   // [comp][mode][ci*16+b]
__device__ u32 g_Ttp[4096 * 1024];                        // [tpos][img] packed(h,l)

// ---------------- helpers ----------------
__device__ __forceinline__ u32 smem_u32(const void* p) {
    u32 a;
    asm("{ .reg .u64 t; cvta.to.shared.u64 t, %1; cvt.u32.u64 %0, t; }" : "=r"(a) : "l"(p));
    return a;
}
__device__ __forceinline__ void ldsm4(u32* r, u32 a) {
    asm volatile("ldmatrix.sync.aligned.m8n8.x4.shared.b16 {%0,%1,%2,%3}, [%4];"
                 : "=r"(r[0]), "=r"(r[1]), "=r"(r[2]), "=r"(r[3]) : "r"(a));
}
__device__ __forceinline__ void ldsm2(u32* r, u32 a) {
    asm volatile("ldmatrix.sync.aligned.m8n8.x2.shared.b16 {%0,%1}, [%2];"
                 : "=r"(r[0]), "=r"(r[1]) : "r"(a));
}
__device__ __forceinline__ void mmabf(float* d, const u32* a, const u32* b) {
    asm volatile("mma.sync.aligned.m16n8k16.row.col.f32.bf16.bf16.f32 "
                 "{%0,%1,%2,%3}, {%4,%5,%6,%7}, {%8,%9}, {%0,%1,%2,%3};"
                 : "+f"(d[0]), "+f"(d[1]), "+f"(d[2]), "+f"(d[3])
                 : "r"(a[0]), "r"(a[1]), "r"(a[2]), "r"(a[3]), "r"(b[0]), "r"(b[1]));
}
__device__ __forceinline__ void cpa(u32 s, const void* g) {
    asm volatile("cp.async.cg.shared.global [%0], [%1], 16;" :: "r"(s), "l"(g));
}
#define CPC()  asm volatile("cp.async.commit_group;" ::: "memory")
#define CPW1() asm volatile("cp.async.wait_group 1;" ::: "memory")
#define CPW0() asm volatile("cp.async.wait_group 0;" ::: "memory")

__device__ __forceinline__ u32 pack_bf(bf16 a, bf16 b) {
    return (u32)__bfloat16_as_ushort(a) | ((u32)__bfloat16_as_ushort(b) << 16);
}
__device__ __forceinline__ void bsplit(float v, bf16& h, bf16& l) {
    h = __float2bfloat16(v);
    l = __float2bfloat16(v - __bfloat162float(h));
}
__device__ __forceinline__ u32 pack_h(float a, float b) {
    bf16 h0, l0, h1, l1; bsplit(a, h0, l0); bsplit(b, h1, l1); return pack_bf(h0, h1);
}
__device__ __forceinline__ u32 pack_l(float a, float b) {
    bf16 h0, l0, h1, l1; bsplit(a, h0, l0); bsplit(b, h1, l1); return pack_bf(l0, l1);
}

// swizzles (conflict-free for 8-row ldsm phases)
__device__ __forceinline__ u32 SWZ(int row, int c) {           // 64B rows
    return (u32)(row * 64 + ((c ^ ((row >> 1) & 3)) << 4));
}
__device__ __forceinline__ u32 swzU(int j, int c16) {          // 512B rows
    return (u32)(j * 512 + ((((c16 ^ j) & 7) | (c16 & 24)) << 4));
}
__device__ __forceinline__ u32 swzW(int m, int c16) {          // 256B rows
    return (u32)(m * 256 + ((((c16 ^ m) & 7) | (c16 & 8)) << 4));
}
__device__ __forceinline__ u32 swzT(int r, int c16) {          // 128B rows
    return (u32)(r * 128 + ((c16 ^ (r & 7)) << 4));
}

// ---------------- K0: split trig tables ----------------
__global__ void k_tables() {
    int a = blockIdx.x, b = threadIdx.x;
    int s = b & 63, k = s - 32;
    int q = ((k * a) % 256 + 256) % 256;
    float sv, cv;
    sincospif((float)q * (1.0f / 128.0f), &sv, &cv);
    float tc = (b < 64) ? cv : sv;
    bf16 h, l;
    bsplit(tc, h, l);
    g_Tch[b * 256 + a] = h; g_Tcl[b * 256 + a] = l;
    g_T5h[a * 128 + b] = h; g_T5l[a * 128 + b] = l;
    int c = b >> 6;
    float a5 = c ? (cv - sv) : (cv + sv);
    bsplit(a5, h, l);
    g_A5h[(c * 256 + a) * 64 + s] = h;
    g_A5l[(c * 256 + a) * 64 + s] = l;
}

// ---------------- Kw: weight transpose + split ----------------
__global__ __launch_bounds__(256) void k_wt(const float* __restrict__ w) {
    __shared__ float tile[64][65];
    int bx = blockIdx.x, o = blockIdx.y;
    int tid = threadIdx.x;
    int tx = tid & 63, tg = tid >> 6;
#pragma unroll
    for (int it = 0; it < 16; it++) {
        int i = tg + it * 4;
        tile[i][tx] = w[(size_t)(i * 64 + o) * 4096 + bx * 64 + tx];
    }
    __syncthreads();
#pragma unroll
    for (int it = 0; it < 16; it++) {
        int xy = tg + it * 4;
        float v = tile[tx][xy];
        bf16 h, l;
        bsplit(v, h, l);
        size_t dst = (size_t)(bx * 64 + xy) * 4096 + o * 64 + tx;
        g_Wth[dst] = h;
        g_Wtl[dst] = l;
    }
}

// ---------------- K12: fused forward (per image) — R13 version ----------------
// smem: Ut_h @0 (64K), Ut_l @65536 (64K), pipeline @131072 (96K)
__global__ __launch_bounds__(512, 1) void k12(const float* __restrict__ x) {
    extern __shared__ char smem[];
    u32 sb = smem_u32(smem);
    const int PIPE = 131072;
    int tid = threadIdx.x, lane = tid & 31, w = tid >> 5;
    int wy = w >> 2, wx = w & 3;        // 4x4 warp grid
    int img = blockIdx.x;
    int g = lane >> 2, cp2 = (lane & 3) * 2;
    int rA = wy * 32 + (lane & 15), cA = lane >> 4;
    int rB = wx * 32 + (lane & 7) + ((lane >> 4) << 3), cB = (lane >> 3) & 1;

    // ======== K1: two passes over m-halves ========
    for (int mh = 0; mh < 2; mh++) {
        const float* xb = x + (size_t)img * 65536 + mh * 128 * 256;
        const int xrow = tid >> 2, xq = tid & 3;
        float c[2][4][4];
#pragma unroll
        for (int i = 0; i < 2; i++)
#pragma unroll
            for (int j = 0; j < 4; j++)
#pragma unroll
                for (int r = 0; r < 4; r++) c[i][j][r] = 0.f;
#pragma unroll
        for (int st = 0; st < 2; st++) {
            u32 b = sb + PIPE + st * 32768;
            cpa(b + SWZ(xrow, xq), &g_Tch[xrow * 256 + st * 32 + xq * 8]);
            cpa(b + 8192 + SWZ(xrow, xq), &g_Tcl[xrow * 256 + st * 32 + xq * 8]);
            CPC();
            const float* s = &xb[xrow * 256 + st * 32 + xq * 8];
            float4 v0 = *(const float4*)s, v1 = *(const float4*)(s + 4);
            u32 h4[4] = {pack_h(v0.x, v0.y), pack_h(v0.z, v0.w), pack_h(v1.x, v1.y), pack_h(v1.z, v1.w)};
            u32 l4[4] = {pack_l(v0.x, v0.y), pack_l(v0.z, v0.w), pack_l(v1.x, v1.y), pack_l(v1.z, v1.w)};
            *(uint4*)(smem + PIPE + st * 32768 + 16384 + SWZ(xrow, xq)) = *(uint4*)h4;
            *(uint4*)(smem + PIPE + st * 32768 + 24576 + SWZ(xrow, xq)) = *(uint4*)l4;
        }
        const int NCH = 8;
        for (int ch = 0; ch < NCH; ch++) {
            if (ch + 1 < NCH) { CPW1(); } else { CPW0(); }
            __syncthreads();
            bool pre = (ch + 2 < NCH);
            float4 v0, v1;
            if (pre) {
                const float* s = &xb[xrow * 256 + (ch + 2) * 32 + xq * 8];
                v0 = *(const float4*)s; v1 = *(const float4*)(s + 4);
                u32 b = sb + PIPE + ((ch + 2) % 3) * 32768;
                cpa(b + SWZ(xrow, xq), &g_Tch[xrow * 256 + (ch + 2) * 32 + xq * 8]);
                cpa(b + 8192 + SWZ(xrow, xq), &g_Tcl[xrow * 256 + (ch + 2) * 32 + xq * 8]);
                CPC();
            }
            u32 base = sb + PIPE + (ch % 3) * 32768;
#pragma unroll
            for (int kk = 0; kk < 2; kk++) {
                int kc = kk * 2;
                u32 ah[2][4], al[2][4], bh[2][4], bl[2][4];
#pragma unroll
                for (int mi = 0; mi < 2; mi++) {
                    u32 ao = SWZ(rA + mi * 16, kc + cA);
                    ldsm4(ah[mi], base + ao);
                    ldsm4(al[mi], base + 8192 + ao);
                }
#pragma unroll
                for (int np = 0; np < 2; np++) {
                    u32 bo = SWZ(rB + np * 16, kc + cB);
                    ldsm4(bh[np], base + 16384 + bo);
                    ldsm4(bl[np], base + 24576 + bo);
                }
#pragma unroll
                for (int mi = 0; mi < 2; mi++)
#pragma unroll
                    for (int ni = 0; ni < 4; ni++)
                        mmabf(c[mi][ni], ah[mi], &bh[ni >> 1][(ni & 1) * 2]);
#pragma unroll
                for (int mi = 0; mi < 2; mi++)
#pragma unroll
                    for (int ni = 0; ni < 4; ni++)
                        mmabf(c[mi][ni], ah[mi], &bl[ni >> 1][(ni & 1) * 2]);
#pragma unroll
                for (int mi = 0; mi < 2; mi++)
#pragma unroll
                    for (int ni = 0; ni < 4; ni++)
                        mmabf(c[mi][ni], al[mi], &bh[ni >> 1][(ni & 1) * 2]);
            }
            if (pre) {
                u32 h4[4] = {pack_h(v0.x, v0.y), pack_h(v0.z, v0.w), pack_h(v1.x, v1.y), pack_h(v1.z, v1.w)};
                u32 l4[4] = {pack_l(v0.x, v0.y), pack_l(v0.z, v0.w), pack_l(v1.x, v1.y), pack_l(v1.z, v1.w)};
                u32 o = PIPE + ((ch + 2) % 3) * 32768;
                *(uint4*)(smem + o + 16384 + SWZ(xrow, xq)) = *(uint4*)h4;
                *(uint4*)(smem + o + 24576 + SWZ(xrow, xq)) = *(uint4*)l4;
            }
        }
#pragma unroll
        for (int mi = 0; mi < 2; mi++)
#pragma unroll
            for (int ni = 0; ni < 4; ni++) {
                int m = mh * 128 + wx * 32 + ni * 8 + cp2;
                int j0 = wy * 32 + mi * 16 + g;
                float* d = c[mi][ni];
                u32 a0 = swzU(j0, m >> 3) + (m & 7) * 2;
                u32 a1 = swzU(j0 + 8, m >> 3) + (m & 7) * 2;
                *(u32*)(smem + a0) = pack_h(d[0], d[1]);
                *(u32*)(smem + 65536 + a0) = pack_l(d[0], d[1]);
                *(u32*)(smem + a1) = pack_h(d[2], d[3]);
                *(u32*)(smem + 65536 + a1) = pack_l(d[2], d[3]);
            }
        __syncthreads();
    }

    // ======== K2: B from smem Ut ========
    {
        const int xrow = tid >> 2, xq = tid & 3;
        float c[2][4][4];
#pragma unroll
        for (int i = 0; i < 2; i++)
#pragma unroll
            for (int j = 0; j < 4; j++)
#pragma unroll
                for (int r = 0; r < 4; r++) c[i][j][r] = 0.f;
#pragma unroll
        for (int st = 0; st < 2; st++) {
            u32 b = sb + PIPE + st * 16384;
            cpa(b + SWZ(xrow, xq), &g_Tch[xrow * 256 + st * 32 + xq * 8]);
            cpa(b + 8192 + SWZ(xrow, xq), &g_Tcl[xrow * 256 + st * 32 + xq * 8]);
            CPC();
        }
        const int NCH = 8;
        for (int ch = 0; ch < NCH; ch++) {
            if (ch + 1 < NCH) { CPW1(); } else { CPW0(); }
            __syncthreads();
            if (ch + 2 < NCH) {
                u32 b = sb + PIPE + ((ch + 2) % 3) * 16384;
                cpa(b + SWZ(xrow, xq), &g_Tch[xrow * 256 + (ch + 2) * 32 + xq * 8]);
                cpa(b + 8192 + SWZ(xrow, xq), &g_Tcl[xrow * 256 + (ch + 2) * 32 + xq * 8]);
                CPC();
            }
            u32 base = sb + PIPE + (ch % 3) * 16384;
#pragma unroll
            for (int kk = 0; kk < 2; kk++) {
                u32 ah[2][4], al[2][4], bh[2][4], bl[2][4];
#pragma unroll
                for (int mi = 0; mi < 2; mi++) {
                    u32 ao = SWZ(rA + mi * 16, kk * 2 + cA);
                    ldsm4(ah[mi], base + ao);
                    ldsm4(al[mi], base + 8192 + ao);
                }
#pragma unroll
                for (int np = 0; np < 2; np++) {
                    int c16 = ch * 4 + kk * 2 + cB;
                    u32 bo = swzU(rB + np * 16, c16);
                    ldsm4(bh[np], sb + bo);
                    ldsm4(bl[np], sb + 65536 + bo);
                }
#pragma unroll
                for (int mi = 0; mi < 2; mi++)
#pragma unroll
                    for (int ni = 0; ni < 4; ni++)
                        mmabf(c[mi][ni], ah[mi], &bh[ni >> 1][(ni & 1) * 2]);
#pragma unroll
                for (int mi = 0; mi < 2; mi++)
#pragma unroll
                    for (int ni = 0; ni < 4; ni++)
                        mmabf(c[mi][ni], ah[mi], &bl[ni >> 1][(ni & 1) * 2]);
#pragma unroll
                for (int mi = 0; mi < 2; mi++)
#pragma unroll
                    for (int ni = 0; ni < 4; ni++)
                        mmabf(c[mi][ni], al[mi], &bh[ni >> 1][(ni & 1) * 2]);
            }
        }
        __syncthreads();
        float* F = (float*)(smem + PIPE);
#pragma unroll
        for (int mi = 0; mi < 2; mi++)
#pragma unroll
            for (int ni = 0; ni < 4; ni++) {
                int col = wx * 32 + ni * 8 + cp2;
                int r0 = wy * 32 + mi * 16 + g;
                float* d = c[mi][ni];
                F[r0 * 132 + col] = d[0];
                F[r0 * 132 + col + 1] = d[1];
                F[(r0 + 8) * 132 + col] = d[2];
                F[(r0 + 8) * 132 + col + 1] = d[3];
            }
        __syncthreads();
        const int b = img >> 6, ic = img & 63;
#pragma unroll
        for (int t = 0; t < 8; t++) {
            int p = tid + t * 512;
            int s1 = p >> 6, s2 = p & 63;
            float r00 = F[s1 * 132 + s2];
            float r01 = F[s1 * 132 + 64 + s2];
            float r10 = F[(64 + s1) * 132 + s2];
            float r11 = F[(64 + s1) * 132 + 64 + s2];
            int a = p * 1024 + ic * 16 + b;
            g_CS[a] = r00 - r11;
            g_CS[4194304 + a] = r10 + r01;
        }
    }
}

// ---------------- K3: paired channel mixing, coalesced Ttp stores ----------------
__global__ __launch_bounds__(256) void k_mix() {
    __shared__ __align__(16) char sm[49152];
    u32 sb = smem_u32(sm);
    const int m0 = blockIdx.x;
    const int s1 = m0 >> 6, s2 = m0 & 63;
    const int f1 = (64 - s1) & 63, f2 = (64 - s2) & 63;
    const int f0 = f1 * 64 + f2;
    if (m0 > f0) return;
    const bool dual = (f0 != m0);
    const int tid = threadIdx.x, lane = tid & 31, w = tid >> 5;
#pragma unroll
    for (int t = 0; t < 2; t++) {
        int f = tid + t * 256;
        int o = f >> 3, c16 = f & 7;
        size_t src = (size_t)m0 * 4096 + o * 64 + c16 * 8;
        size_t srcf = (size_t)f0 * 4096 + o * 64 + c16 * 8;
        cpa(sb + 16384 + swzT(o, c16), &g_Wth[src]);
        cpa(sb + 24576 + swzT(o, c16), &g_Wtl[src]);
        cpa(sb + 32768 + swzT(o, c16), &g_Wth[srcf]);
        cpa(sb + 40960 + swzT(o, c16), &g_Wtl[srcf]);
    }
    CPC();
    {
        float4 cv = *(const float4*)&g_CS[m0 * 1024 + tid * 4];
        float4 sv = *(const float4*)&g_CS[4194304 + m0 * 1024 + tid * 4];
        float cva[4] = {cv.x, cv.y, cv.z, cv.w}, sva[4] = {sv.x, sv.y, sv.z, sv.w};
#pragma unroll
        for (int q = 0; q < 4; q++) {
            int j = tid * 4 + q;
            int b = j & 15, ci = j >> 4;
            u32 a = swzT(b, ci >> 3) + (ci & 7) * 2;
            bf16 h, l;
            bsplit(cva[q], h, l);
            *(unsigned short*)(sm + a) = __bfloat16_as_ushort(h);
            *(unsigned short*)(sm + 2048 + a) = __bfloat16_as_ushort(l);
            bsplit(sva[q], h, l);
            *(unsigned short*)(sm + 4096 + a) = __bfloat16_as_ushort(h);
            *(unsigned short*)(sm + 6144 + a) = __bfloat16_as_ushort(l);
        }
        if (dual) {
            float4 cvf = *(const float4*)&g_CS[f0 * 1024 + tid * 4];
            float4 svf = *(const float4*)&g_CS[4194304 + f0 * 1024 + tid * 4];
            float cvb[4] = {cvf.x, cvf.y, cvf.z, cvf.w}, svb[4] = {svf.x, svf.y, svf.z, svf.w};
#pragma unroll
            for (int q = 0; q < 4; q++) {
                int j = tid * 4 + q;
                int b = j & 15, ci = j >> 4;
                u32 a = swzT(b, ci >> 3) + (ci & 7) * 2;
                bf16 h, l;
                bsplit(cvb[q], h, l);
                *(unsigned short*)(sm + 8192 + a) = __bfloat16_as_ushort(h);
                *(unsigned short*)(sm + 10240 + a) = __bfloat16_as_ushort(l);
                bsplit(svb[q], h, l);
                *(unsigned short*)(sm + 12288 + a) = __bfloat16_as_ushort(h);
                *(unsigned short*)(sm + 14336 + a) = __bfloat16_as_ushort(l);
            }
        }
    }
    CPW0();
    __syncthreads();
    float acc0[4] = {0.f, 0.f, 0.f, 0.f};
    float acc1[4] = {0.f, 0.f, 0.f, 0.f};
    const int o0 = w * 8;
    const int arow = lane & 15, ac = lane >> 4;
    const int brow = o0 + (lane & 7), bc = (lane >> 3) & 1;
#pragma unroll
    for (int kc = 0; kc < 4; kc++) {
        u32 ao = swzT(arow, kc * 2 + ac);
        u32 bo = swzT(brow, kc * 2 + bc);
        u32 bh[2], bl[2], brh[2], brl[2];
        ldsm2(bh, sb + 16384 + bo);
        ldsm2(bl, sb + 24576 + bo);
        ldsm2(brh, sb + 32768 + bo);
        ldsm2(brl, sb + 40960 + bo);
        {
            u32 ach[4], acl[4], ash[4], asl[4];
            ldsm4(ach, sb + ao);
            ldsm4(acl, sb + 2048 + ao);
            ldsm4(ash, sb + 4096 + ao);
            ldsm4(asl, sb + 6144 + ao);
            mmabf(acc0, ach, bh);
            mmabf(acc0, ach, bl);
            mmabf(acc0, acl, bh);
            mmabf(acc0, ash, brh);
            mmabf(acc0, ash, brl);
            mmabf(acc0, asl, brh);
        }
        if (dual) {
            u32 ach[4], acl[4], ash[4], asl[4];
            ldsm4(ach, sb + 8192 + ao);
            ldsm4(acl, sb + 10240 + ao);
            ldsm4(ash, sb + 12288 + ao);
            ldsm4(asl, sb + 14336 + ao);
            mmabf(acc1, ach, brh);
            mmabf(acc1, ach, brl);
            mmabf(acc1, acl, brh);
            mmabf(acc1, ash, bh);
            mmabf(acc1, ash, bl);
            mmabf(acc1, asl, bh);
        }
    }
    // epilogue: coalesced stores to [tpos][img]
    const int g = lane >> 2, cp2 = (lane & 3) * 2;
    const int tpos0 = s2 * 64 + s1;
    const int tpos1 = f2 * 64 + f1;
#pragma unroll
    for (int half = 0; half < 2; half++) {
        int b = g + half * 8;
        bf16 h, l;
        bsplit(acc0[half * 2], h, l);
        g_Ttp[(size_t)tpos0 * 1024 + b * 64 + o0 + cp2] = pack_bf(h, l);
        bsplit(acc0[half * 2 + 1], h, l);
        g_Ttp[(size_t)tpos0 * 1024 + b * 64 + o0 + cp2 + 1] = pack_bf(h, l);
        if (dual) {
            bsplit(acc1[half * 2], h, l);
            g_Ttp[(size_t)tpos1 * 1024 + b * 64 + o0 + cp2] = pack_bf(h, l);
            bsplit(acc1[half * 2 + 1], h, l);
            g_Ttp[(size_t)tpos1 * 1024 + b * 64 + o0 + cp2 + 1] = pack_bf(h, l);
        }
    }
}

// ---------------- K45: fused inverse (per image) ----------------
__global__ __launch_bounds__(512, 1) void k45(const float* __restrict__ bias,
                                              float* __restrict__ out) {
    extern __shared__ char smem[];
    u32 sb = smem_u32(smem);
    const int PIPE = 131072, TT = 196608;
    int tid = threadIdx.x, lane = tid & 31, w = tid >> 5;
    int wy = w >> 1, wx = w & 1;
    int img = blockIdx.x;
    int g = lane >> 2, cp2 = (lane & 3) * 2;

    auto issueA = [&](int slot) {
        int cc = slot >> 1, k0 = (slot & 1) * 32;
        const bf16* Ah = g_A5h + cc * 16384;
        const bf16* Al = g_A5l + cc * 16384;
        u32 b = sb + PIPE + (slot & 1) * 32768;
#pragma unroll
        for (int t = 0; t < 2; t++) {
            int f = tid + t * 512, row = f >> 2, q = f & 3;
            cpa(b + SWZ(row, q), &Ah[row * 64 + k0 + q * 8]);
            cpa(b + 16384 + SWZ(row, q), &Al[row * 64 + k0 + q * 8]);
        }
        CPC();
    };
    issueA(0); issueA(1);

    // unpack packed Tot (gather [tpos][img], L2-resident) into h/l tiles
#pragma unroll
    for (int t = 0; t < 8; t++) {
        int p = tid + t * 512;
        u32 v = g_Ttp[(size_t)p * 1024 + img];
        int r = p >> 6, cc = p & 63;
        u32 a = swzT(r, cc >> 3) + (cc & 7) * 2;
        *(unsigned short*)(smem + TT + a) = (unsigned short)(v & 0xFFFF);
        *(unsigned short*)(smem + TT + 8192 + a) = (unsigned short)(v >> 16);
    }

    int rA = wy * 32 + (lane & 15), cA = lane >> 4;
    int rB = wx * 32 + (lane & 7) + ((lane >> 4) << 3), cB = (lane >> 3) & 1;
    for (int cpass = 0; cpass < 2; cpass++) {
        float acc[2][4][4];
#pragma unroll
        for (int i = 0; i < 2; i++)
#pragma unroll
            for (int j = 0; j < 4; j++)
#pragma unroll
                for (int r = 0; r < 4; r++) acc[i][j][r] = 0.f;
        for (int k = 0; k < 2; k++) {
            int slot = cpass * 2 + k;
            if (slot < 3) { CPW1(); } else { CPW0(); }
            __syncthreads();
            u32 stg = sb + PIPE + (slot & 1) * 32768;
#pragma unroll
            for (int kk = 0; kk < 2; kk++) {
                u32 ah[2][4], al[2][4], bh[2][4], bl[2][4];
#pragma unroll
                for (int mi = 0; mi < 2; mi++) {
                    u32 ao = SWZ(rA + mi * 16, kk * 2 + cA);
                    ldsm4(ah[mi], stg + ao);
                    ldsm4(al[mi], stg + 16384 + ao);
                }
#pragma unroll
                for (int np = 0; np < 2; np++) {
                    int c16 = k * 4 + kk * 2 + cB;
                    u32 bo = swzT(rB + np * 16, c16);
                    ldsm4(bh[np], sb + TT + bo);
                    ldsm4(bl[np], sb + TT + 8192 + bo);
                }
#pragma unroll
                for (int mi = 0; mi < 2; mi++)
#pragma unroll
                    for (int ni = 0; ni < 4; ni++)
                        mmabf(acc[mi][ni], ah[mi], &bh[ni >> 1][(ni & 1) * 2]);
#pragma unroll
                for (int mi = 0; mi < 2; mi++)
#pragma unroll
                    for (int ni = 0; ni < 4; ni++)
                        mmabf(acc[mi][ni], ah[mi], &bl[ni >> 1][(ni & 1) * 2]);
#pragma unroll
                for (int mi = 0; mi < 2; mi++)
#pragma unroll
                    for (int ni = 0; ni < 4; ni++)
                        mmabf(acc[mi][ni], al[mi], &bh[ni >> 1][(ni & 1) * 2]);
            }
            __syncthreads();
            if (slot + 2 < 4) issueA(slot + 2);
        }
#pragma unroll
        for (int mi = 0; mi < 2; mi++)
#pragma unroll
            for (int ni = 0; ni < 4; ni++) {
                int col = cpass * 64 + wx * 32 + ni * 8 + cp2;
                int m0 = wy * 32 + mi * 16 + g;
                float* d = acc[mi][ni];
                u32 a0 = swzW(m0, col >> 3) + (col & 7) * 2;
                u32 a1 = swzW(m0 + 8, col >> 3) + (col & 7) * 2;
                *(u32*)(smem + a0) = pack_h(d[0], d[1]);
                *(u32*)(smem + 65536 + a0) = pack_l(d[0], d[1]);
                *(u32*)(smem + a1) = pack_h(d[2], d[3]);
                *(u32*)(smem + 65536 + a1) = pack_l(d[2], d[3]);
            }
    }
    __syncthreads();

    const float bv = bias[img & 63];
    const float sc = 1.0f / 65536.0f;
    int rB5 = wx * 64 + (lane & 7) + ((lane >> 4) << 3);
    for (int nh = 0; nh < 2; nh++) {
        float c5[2][8][4];
#pragma unroll
        for (int i = 0; i < 2; i++)
#pragma unroll
            for (int j = 0; j < 8; j++)
#pragma unroll
                for (int r = 0; r < 4; r++) c5[i][j][r] = 0.f;
        int xrow = tid >> 2, xq = tid & 3;
#pragma unroll
        for (int st = 0; st < 2; st++) {
            u32 b = sb + PIPE + st * 16384;
            cpa(b + SWZ(xrow, xq), &g_T5h[(nh * 128 + xrow) * 128 + st * 32 + xq * 8]);
            cpa(b + 8192 + SWZ(xrow, xq), &g_T5l[(nh * 128 + xrow) * 128 + st * 32 + xq * 8]);
            CPC();
        }
        for (int ch = 0; ch < 4; ch++) {
            if (ch < 3) { CPW1(); } else { CPW0(); }
            __syncthreads();
            if (ch + 2 < 4) {
                u32 b = sb + PIPE + ((ch + 2) % 3) * 16384;
                cpa(b + SWZ(xrow, xq), &g_T5h[(nh * 128 + xrow) * 128 + (ch + 2) * 32 + xq * 8]);
                cpa(b + 8192 + SWZ(xrow, xq), &g_T5l[(nh * 128 + xrow) * 128 + (ch + 2) * 32 + xq * 8]);
                CPC();
            }
            u32 stg = sb + PIPE + (ch % 3) * 16384;
#pragma unroll
            for (int kk = 0; kk < 2; kk++) {
                u32 ah[2][4], al[2][4], bh[4][4], bl[4][4];
#pragma unroll
                for (int mi = 0; mi < 2; mi++) {
                    int c16 = ch * 4 + kk * 2 + cA;
                    u32 ao = swzW(rA + mi * 16, c16);
                    ldsm4(ah[mi], sb + ao);
                    ldsm4(al[mi], sb + 65536 + ao);
                }
#pragma unroll
                for (int np = 0; np < 4; np++) {
                    u32 bo = SWZ(rB5 + np * 16, kk * 2 + cB);
                    ldsm4(bh[np], stg + bo);
                    ldsm4(bl[np], stg + 8192 + bo);
                }
#pragma unroll
                for (int mi = 0; mi < 2; mi++)
#pragma unroll
                    for (int ni = 0; ni < 8; ni++)
                        mmabf(c5[mi][ni], ah[mi], &bh[ni >> 1][(ni & 1) * 2]);
#pragma unroll
                for (int mi = 0; mi < 2; mi++)
#pragma unroll
                    for (int ni = 0; ni < 8; ni++)
                        mmabf(c5[mi][ni], ah[mi], &bl[ni >> 1][(ni & 1) * 2]);
#pragma unroll
                for (int mi = 0; mi < 2; mi++)
#pragma unroll
                    for (int ni = 0; ni < 8; ni++)
                        mmabf(c5[mi][ni], al[mi], &bh[ni >> 1][(ni & 1) * 2]);
            }
        }
#pragma unroll
        for (int mi = 0; mi < 2; mi++)
#pragma unroll
            for (int ni = 0; ni < 8; ni++) {
                int col = nh * 128 + wx * 64 + ni * 8 + cp2;
                float* d = c5[mi][ni];
#pragma unroll
                for (int half = 0; half < 2; half++) {
                    int m = wy * 32 + mi * 16 + g + half * 8;
                    float2 v;
                    v.x = fmaxf(fmaf(d[half * 2], sc, bv), 0.f);
                    v.y = fmaxf(fmaf(d[half * 2 + 1], sc, bv), 0.f);
                    *(float2*)&out[(size_t)img * 65536 + m * 256 + col] = v;
                }
            }
        __syncthreads();
    }
}

extern "C" void kernel_launch(void* const* d_in, const int* in_sizes, int n_in,
                              void* d_out, int out_size) {
    const float* x = (const float*)d_in[0];
    const float* wgt = (const float*)d_in[1];
    const float* bias = (const float*)d_in[2];
    float* out = (float*)d_out;

    static cudaStream_t side = nullptr;
    static cudaEvent_t evFork = nullptr, evJoin = nullptr;
    if (!side) {
        cudaStreamCreateWithFlags(&side, cudaStreamNonBlocking);
        cudaEventCreateWithFlags(&evFork, cudaEventDisableTiming);
        cudaEventCreateWithFlags(&evJoin, cudaEventDisableTiming);
    }
    cudaFuncSetAttribute(k12, cudaFuncAttributeMaxDynamicSharedMemorySize, 229376);
    cudaFuncSetAttribute(k45, cudaFuncAttributeMaxDynamicSharedMemorySize, 212992);

    cudaEventRecord(evFork, 0);
    cudaStreamWaitEvent(side, evFork, 0);
    k_wt<<<dim3(64, 64), 256, 0, side>>>(wgt);
    cudaEventRecord(evJoin, side);

    k_tables<<<256, 128>>>();
    k12<<<1024, 512, 229376>>>(x);

    cudaStreamWaitEvent(0, evJoin, 0);
    k_mix<<<4096, 256>>>();
    k45<<<1024, 512, 212992>>>(bias, out);
}

// round 17
// speedup vs baseline: 1.1981x; 1.0872x over previous
#include <cuda_runtime.h>
#include <cuda_bf16.h>
#include <cstdint>

// HartleySpectralConv2d B=16,CI=CO=64,H=W=256, modes 64x64.
// Split-bf16 HMMA. R17 = R13 k12/k45 + tpos-major k_mix stores + k_tt
// transpose (coalesced both sides).

using bf16 = __nv_bfloat16;
using u32 = uint32_t; using ull = unsigned long long;

__device__ bf16 g_Tch[128 * 256], g_Tcl[128 * 256];       // [j][a] K-major
__device__ bf16 g_A5h[2 * 256 * 64], g_A5l[2 * 256 * 64]; // [(c*256+m)][s1]
__device__ bf16 g_T5h[256 * 128], g_T5l[256 * 128];       // [n][c*64+s2]
__device__ bf16 g_Wth[4096 * 4096], g_Wtl[4096 * 4096];   // [mode][o*64+i] split
__device__ float g_CS[2 * 4096 * 1024];                   // [comp][mode][ci*16+b]
__device__ u32 g_Ttp[4096 * 1024];                        // [tpos][img] packed(h,l)
__device__ u32 g_Tt2[1024 * 4096];                        // [img][tpos] packed(h,l)

// ---------------- helpers ----------------
__device__ __forceinline__ u32 smem_u32(const void* p) {
    u32 a;
    asm("{ .reg .u64 t; cvta.to.shared.u64 t, %1; cvt.u32.u64 %0, t; }" : "=r"(a) : "l"(p));
    return a;
}
__device__ __forceinline__ void ldsm4(u32* r, u32 a) {
    asm volatile("ldmatrix.sync.aligned.m8n8.x4.shared.b16 {%0,%1,%2,%3}, [%4];"
                 : "=r"(r[0]), "=r"(r[1]), "=r"(r[2]), "=r"(r[3]) : "r"(a));
}
__device__ __forceinline__ void ldsm2(u32* r, u32 a) {
    asm volatile("ldmatrix.sync.aligned.m8n8.x2.shared.b16 {%0,%1}, [%2];"
                 : "=r"(r[0]), "=r"(r[1]) : "r"(a));
}
__device__ __forceinline__ void mmabf(float* d, const u32* a, const u32* b) {
    asm volatile("mma.sync.aligned.m16n8k16.row.col.f32.bf16.bf16.f32 "
                 "{%0,%1,%2,%3}, {%4,%5,%6,%7}, {%8,%9}, {%0,%1,%2,%3};"
                 : "+f"(d[0]), "+f"(d[1]), "+f"(d[2]), "+f"(d[3])
                 : "r"(a[0]), "r"(a[1]), "r"(a[2]), "r"(a[3]), "r"(b[0]), "r"(b[1]));
}
__device__ __forceinline__ void cpa(u32 s, const void* g) {
    asm volatile("cp.async.cg.shared.global [%0], [%1], 16;" :: "r"(s), "l"(g));
}
#define CPC()  asm volatile("cp.async.commit_group;" ::: "memory")
#define CPW1() asm volatile("cp.async.wait_group 1;" ::: "memory")
#define CPW0() asm volatile("cp.async.wait_group 0;" ::: "memory")

__device__ __forceinline__ u32 pack_bf(bf16 a, bf16 b) {
    return (u32)__bfloat16_as_ushort(a) | ((u32)__bfloat16_as_ushort(b) << 16);
}
__device__ __forceinline__ void bsplit(float v, bf16& h, bf16& l) {
    h = __float2bfloat16(v);
    l = __float2bfloat16(v - __bfloat162float(h));
}
__device__ __forceinline__ u32 pack_h(float a, float b) {
    bf16 h0, l0, h1, l1; bsplit(a, h0, l0); bsplit(b, h1, l1); return pack_bf(h0, h1);
}
__device__ __forceinline__ u32 pack_l(float a, float b) {
    bf16 h0, l0, h1, l1; bsplit(a, h0, l0); bsplit(b, h1, l1); return pack_bf(l0, l1);
}

// swizzles (conflict-free for 8-row ldsm phases)
__device__ __forceinline__ u32 SWZ(int row, int c) {           // 64B rows
    return (u32)(row * 64 + ((c ^ ((row >> 1) & 3)) << 4));
}
__device__ __forceinline__ u32 swzU(int j, int c16) {          // 512B rows
    return (u32)(j * 512 + ((((c16 ^ j) & 7) | (c16 & 24)) << 4));
}
__device__ __forceinline__ u32 swzW(int m, int c16) {          // 256B rows
    return (u32)(m * 256 + ((((c16 ^ m) & 7) | (c16 & 8)) << 4));
}
__device__ __forceinline__ u32 swzT(int r, int c16) {          // 128B rows
    return (u32)(r * 128 + ((c16 ^ (r & 7)) << 4));
}

// ---------------- K0: split trig tables ----------------
__global__ void k_tables() {
    int a = blockIdx.x, b = threadIdx.x;
    int s = b & 63, k = s - 32;
    int q = ((k * a) % 256 + 256) % 256;
    float sv, cv;
    sincospif((float)q * (1.0f / 128.0f), &sv, &cv);
    float tc = (b < 64) ? cv : sv;
    bf16 h, l;
    bsplit(tc, h, l);
    g_Tch[b * 256 + a] = h; g_Tcl[b * 256 + a] = l;
    g_T5h[a * 128 + b] = h; g_T5l[a * 128 + b] = l;
    int c = b >> 6;
    float a5 = c ? (cv - sv) : (cv + sv);
    bsplit(a5, h, l);
    g_A5h[(c * 256 + a) * 64 + s] = h;
    g_A5l[(c * 256 + a) * 64 + s] = l;
}

// ---------------- Kw: weight transpose + split ----------------
__global__ __launch_bounds__(256) void k_wt(const float* __restrict__ w) {
    __shared__ float tile[64][65];
    int bx = blockIdx.x, o = blockIdx.y;
    int tid = threadIdx.x;
    int tx = tid & 63, tg = tid >> 6;
#pragma unroll
    for (int it = 0; it < 16; it++) {
        int i = tg + it * 4;
        tile[i][tx] = w[(size_t)(i * 64 + o) * 4096 + bx * 64 + tx];
    }
    __syncthreads();
#pragma unroll
    for (int it = 0; it < 16; it++) {
        int xy = tg + it * 4;
        float v = tile[tx][xy];
        bf16 h, l;
        bsplit(v, h, l);
        size_t dst = (size_t)(bx * 64 + xy) * 4096 + o * 64 + tx;
        g_Wth[dst] = h;
        g_Wtl[dst] = l;
    }
}

// ---------------- K_tt: transpose Ttp [tpos][img] -> Tt2 [img][tpos] ----------------
__global__ void k_tt() {
    __shared__ u32 t[32][33];
    int i0 = blockIdx.x * 32, p0 = blockIdx.y * 32;
    int tx = threadIdx.x, ty = threadIdx.y;   // (32, 8)
#pragma unroll
    for (int r = 0; r < 32; r += 8)
        t[ty + r][tx] = g_Ttp[(size_t)(p0 + ty + r) * 1024 + i0 + tx];
    __syncthreads();
#pragma unroll
    for (int r = 0; r < 32; r += 8)
        g_Tt2[(size_t)(i0 + ty + r) * 4096 + p0 + tx] = t[tx][ty + r];
}

// ---------------- K12: fused forward (per image) — R13 version ----------------
// smem: Ut_h @0 (64K), Ut_l @65536 (64K), pipeline @131072 (96K)
__global__ __launch_bounds__(512, 1) void k12(const float* __restrict__ x) {
    extern __shared__ char smem[];
    u32 sb = smem_u32(smem);
    const int PIPE = 131072;
    int tid = threadIdx.x, lane = tid & 31, w = tid >> 5;
    int wy = w >> 2, wx = w & 3;        // 4x4 warp grid
    int img = blockIdx.x;
    int g = lane >> 2, cp2 = (lane & 3) * 2;
    int rA = wy * 32 + (lane & 15), cA = lane >> 4;
    int rB = wx * 32 + (lane & 7) + ((lane >> 4) << 3), cB = (lane >> 3) & 1;

    // ======== K1: two passes over m-halves ========
    for (int mh = 0; mh < 2; mh++) {
        const float* xb = x + (size_t)img * 65536 + mh * 128 * 256;
        const int xrow = tid >> 2, xq = tid & 3;
        float c[2][4][4];
#pragma unroll
        for (int i = 0; i < 2; i++)
#pragma unroll
            for (int j = 0; j < 4; j++)
#pragma unroll
                for (int r = 0; r < 4; r++) c[i][j][r] = 0.f;
#pragma unroll
        for (int st = 0; st < 2; st++) {
            u32 b = sb + PIPE + st * 32768;
            cpa(b + SWZ(xrow, xq), &g_Tch[xrow * 256 + st * 32 + xq * 8]);
            cpa(b + 8192 + SWZ(xrow, xq), &g_Tcl[xrow * 256 + st * 32 + xq * 8]);
            CPC();
            const float* s = &xb[xrow * 256 + st * 32 + xq * 8];
            float4 v0 = *(const float4*)s, v1 = *(const float4*)(s + 4);
            u32 h4[4] = {pack_h(v0.x, v0.y), pack_h(v0.z, v0.w), pack_h(v1.x, v1.y), pack_h(v1.z, v1.w)};
            u32 l4[4] = {pack_l(v0.x, v0.y), pack_l(v0.z, v0.w), pack_l(v1.x, v1.y), pack_l(v1.z, v1.w)};
            *(uint4*)(smem + PIPE + st * 32768 + 16384 + SWZ(xrow, xq)) = *(uint4*)h4;
            *(uint4*)(smem + PIPE + st * 32768 + 24576 + SWZ(xrow, xq)) = *(uint4*)l4;
        }
        const int NCH = 8;
        for (int ch = 0; ch < NCH; ch++) {
            if (ch + 1 < NCH) { CPW1(); } else { CPW0(); }
            __syncthreads();
            bool pre = (ch + 2 < NCH);
            float4 v0, v1;
            if (pre) {
                const float* s = &xb[xrow * 256 + (ch + 2) * 32 + xq * 8];
                v0 = *(const float4*)s; v1 = *(const float4*)(s + 4);
                u32 b = sb + PIPE + ((ch + 2) % 3) * 32768;
                cpa(b + SWZ(xrow, xq), &g_Tch[xrow * 256 + (ch + 2) * 32 + xq * 8]);
                cpa(b + 8192 + SWZ(xrow, xq), &g_Tcl[xrow * 256 + (ch + 2) * 32 + xq * 8]);
                CPC();
            }
            u32 base = sb + PIPE + (ch % 3) * 32768;
#pragma unroll
            for (int kk = 0; kk < 2; kk++) {
                int kc = kk * 2;
                u32 ah[2][4], al[2][4], bh[2][4], bl[2][4];
#pragma unroll
                for (int mi = 0; mi < 2; mi++) {
                    u32 ao = SWZ(rA + mi * 16, kc + cA);
                    ldsm4(ah[mi], base + ao);
                    ldsm4(al[mi], base + 8192 + ao);
                }
#pragma unroll
                for (int np = 0; np < 2; np++) {
                    u32 bo = SWZ(rB + np * 16, kc + cB);
                    ldsm4(bh[np], base + 16384 + bo);
                    ldsm4(bl[np], base + 24576 + bo);
                }
#pragma unroll
                for (int mi = 0; mi < 2; mi++)
#pragma unroll
                    for (int ni = 0; ni < 4; ni++)
                        mmabf(c[mi][ni], ah[mi], &bh[ni >> 1][(ni & 1) * 2]);
#pragma unroll
                for (int mi = 0; mi < 2; mi++)
#pragma unroll
                    for (int ni = 0; ni < 4; ni++)
                        mmabf(c[mi][ni], ah[mi], &bl[ni >> 1][(ni & 1) * 2]);
#pragma unroll
                for (int mi = 0; mi < 2; mi++)
#pragma unroll
                    for (int ni = 0; ni < 4; ni++)
                        mmabf(c[mi][ni], al[mi], &bh[ni >> 1][(ni & 1) * 2]);
            }
            if (pre) {
                u32 h4[4] = {pack_h(v0.x, v0.y), pack_h(v0.z, v0.w), pack_h(v1.x, v1.y), pack_h(v1.z, v1.w)};
                u32 l4[4] = {pack_l(v0.x, v0.y), pack_l(v0.z, v0.w), pack_l(v1.x, v1.y), pack_l(v1.z, v1.w)};
                u32 o = PIPE + ((ch + 2) % 3) * 32768;
                *(uint4*)(smem + o + 16384 + SWZ(xrow, xq)) = *(uint4*)h4;
                *(uint4*)(smem + o + 24576 + SWZ(xrow, xq)) = *(uint4*)l4;
            }
        }
#pragma unroll
        for (int mi = 0; mi < 2; mi++)
#pragma unroll
            for (int ni = 0; ni < 4; ni++) {
                int m = mh * 128 + wx * 32 + ni * 8 + cp2;
                int j0 = wy * 32 + mi * 16 + g;
                float* d = c[mi][ni];
                u32 a0 = swzU(j0, m >> 3) + (m & 7) * 2;
                u32 a1 = swzU(j0 + 8, m >> 3) + (m & 7) * 2;
                *(u32*)(smem + a0) = pack_h(d[0], d[1]);
                *(u32*)(smem + 65536 + a0) = pack_l(d[0], d[1]);
                *(u32*)(smem + a1) = pack_h(d[2], d[3]);
                *(u32*)(smem + 65536 + a1) = pack_l(d[2], d[3]);
            }
        __syncthreads();
    }

    // ======== K2: B from smem Ut ========
    {
        const int xrow = tid >> 2, xq = tid & 3;
        float c[2][4][4];
#pragma unroll
        for (int i = 0; i < 2; i++)
#pragma unroll
            for (int j = 0; j < 4; j++)
#pragma unroll
                for (int r = 0; r < 4; r++) c[i][j][r] = 0.f;
#pragma unroll
        for (int st = 0; st < 2; st++) {
            u32 b = sb + PIPE + st * 16384;
            cpa(b + SWZ(xrow, xq), &g_Tch[xrow * 256 + st * 32 + xq * 8]);
            cpa(b + 8192 + SWZ(xrow, xq), &g_Tcl[xrow * 256 + st * 32 + xq * 8]);
            CPC();
        }
        const int NCH = 8;
        for (int ch = 0; ch < NCH; ch++) {
            if (ch + 1 < NCH) { CPW1(); } else { CPW0(); }
            __syncthreads();
            if (ch + 2 < NCH) {
                u32 b = sb + PIPE + ((ch + 2) % 3) * 16384;
                cpa(b + SWZ(xrow, xq), &g_Tch[xrow * 256 + (ch + 2) * 32 + xq * 8]);
                cpa(b + 8192 + SWZ(xrow, xq), &g_Tcl[xrow * 256 + (ch + 2) * 32 + xq * 8]);
                CPC();
            }
            u32 base = sb + PIPE + (ch % 3) * 16384;
#pragma unroll
            for (int kk = 0; kk < 2; kk++) {
                u32 ah[2][4], al[2][4], bh[2][4], bl[2][4];
#pragma unroll
                for (int mi = 0; mi < 2; mi++) {
                    u32 ao = SWZ(rA + mi * 16, kk * 2 + cA);
                    ldsm4(ah[mi], base + ao);
                    ldsm4(al[mi], base + 8192 + ao);
                }
#pragma unroll
                for (int np = 0; np < 2; np++) {
                    int c16 = ch * 4 + kk * 2 + cB;
                    u32 bo = swzU(rB + np * 16, c16);
                    ldsm4(bh[np], sb + bo);
                    ldsm4(bl[np], sb + 65536 + bo);
                }
#pragma unroll
                for (int mi = 0; mi < 2; mi++)
#pragma unroll
                    for (int ni = 0; ni < 4; ni++)
                        mmabf(c[mi][ni], ah[mi], &bh[ni >> 1][(ni & 1) * 2]);
#pragma unroll
                for (int mi = 0; mi < 2; mi++)
#pragma unroll
                    for (int ni = 0; ni < 4; ni++)
                        mmabf(c[mi][ni], ah[mi], &bl[ni >> 1][(ni & 1) * 2]);
#pragma unroll
                for (int mi = 0; mi < 2; mi++)
#pragma unroll
                    for (int ni = 0; ni < 4; ni++)
                        mmabf(c[mi][ni], al[mi], &bh[ni >> 1][(ni & 1) * 2]);
            }
        }
        __syncthreads();
        float* F = (float*)(smem + PIPE);
#pragma unroll
        for (int mi = 0; mi < 2; mi++)
#pragma unroll
            for (int ni = 0; ni < 4; ni++) {
                int col = wx * 32 + ni * 8 + cp2;
                int r0 = wy * 32 + mi * 16 + g;
                float* d = c[mi][ni];
                F[r0 * 132 + col] = d[0];
                F[r0 * 132 + col + 1] = d[1];
                F[(r0 + 8) * 132 + col] = d[2];
                F[(r0 + 8) * 132 + col + 1] = d[3];
            }
        __syncthreads();
        const int b = img >> 6, ic = img & 63;
#pragma unroll
        for (int t = 0; t < 8; t++) {
            int p = tid + t * 512;
            int s1 = p >> 6, s2 = p & 63;
            float r00 = F[s1 * 132 + s2];
            float r01 = F[s1 * 132 + 64 + s2];
            float r10 = F[(64 + s1) * 132 + s2];
            float r11 = F[(64 + s1) * 132 + 64 + s2];
            int a = p * 1024 + ic * 16 + b;
            g_CS[a] = r00 - r11;
            g_CS[4194304 + a] = r10 + r01;
        }
    }
}

// ---------------- K3: paired channel mixing, coalesced Ttp stores ----------------
__global__ __launch_bounds__(256) void k_mix() {
    __shared__ __align__(16) char sm[49152];
    u32 sb = smem_u32(sm);
    const int m0 = blockIdx.x;
    const int s1 = m0 >> 6, s2 = m0 & 63;
    const int f1 = (64 - s1) & 63, f2 = (64 - s2) & 63;
    const int f0 = f1 * 64 + f2;
    if (m0 > f0) return;
    const bool dual = (f0 != m0);
    const int tid = threadIdx.x, lane = tid & 31, w = tid >> 5;
#pragma unroll
    for (int t = 0; t < 2; t++) {
        int f = tid + t * 256;
        int o = f >> 3, c16 = f & 7;
        size_t src = (size_t)m0 * 4096 + o * 64 + c16 * 8;
        size_t srcf = (size_t)f0 * 4096 + o * 64 + c16 * 8;
        cpa(sb + 16384 + swzT(o, c16), &g_Wth[src]);
        cpa(sb + 24576 + swzT(o, c16), &g_Wtl[src]);
        cpa(sb + 32768 + swzT(o, c16), &g_Wth[srcf]);
        cpa(sb + 40960 + swzT(o, c16), &g_Wtl[srcf]);
    }
    CPC();
    {
        float4 cv = *(const float4*)&g_CS[m0 * 1024 + tid * 4];
        float4 sv = *(const float4*)&g_CS[4194304 + m0 * 1024 + tid * 4];
        float cva[4] = {cv.x, cv.y, cv.z, cv.w}, sva[4] = {sv.x, sv.y, sv.z, sv.w};
#pragma unroll
        for (int q = 0; q < 4; q++) {
            int j = tid * 4 + q;
            int b = j & 15, ci = j >> 4;
            u32 a = swzT(b, ci >> 3) + (ci & 7) * 2;
            bf16 h, l;
            bsplit(cva[q], h, l);
            *(unsigned short*)(sm + a) = __bfloat16_as_ushort(h);
            *(unsigned short*)(sm + 2048 + a) = __bfloat16_as_ushort(l);
            bsplit(sva[q], h, l);
            *(unsigned short*)(sm + 4096 + a) = __bfloat16_as_ushort(h);
            *(unsigned short*)(sm + 6144 + a) = __bfloat16_as_ushort(l);
        }
        if (dual) {
            float4 cvf = *(const float4*)&g_CS[f0 * 1024 + tid * 4];
            float4 svf = *(const float4*)&g_CS[4194304 + f0 * 1024 + tid * 4];
            float cvb[4] = {cvf.x, cvf.y, cvf.z, cvf.w}, svb[4] = {svf.x, svf.y, svf.z, svf.w};
#pragma unroll
            for (int q = 0; q < 4; q++) {
                int j = tid * 4 + q;
                int b = j & 15, ci = j >> 4;
                u32 a = swzT(b, ci >> 3) + (ci & 7) * 2;
                bf16 h, l;
                bsplit(cvb[q], h, l);
                *(unsigned short*)(sm + 8192 + a) = __bfloat16_as_ushort(h);
                *(unsigned short*)(sm + 10240 + a) = __bfloat16_as_ushort(l);
                bsplit(svb[q], h, l);
                *(unsigned short*)(sm + 12288 + a) = __bfloat16_as_ushort(h);
                *(unsigned short*)(sm + 14336 + a) = __bfloat16_as_ushort(l);
            }
        }
    }
    CPW0();
    __syncthreads();
    float acc0[4] = {0.f, 0.f, 0.f, 0.f};
    float acc1[4] = {0.f, 0.f, 0.f, 0.f};
    const int o0 = w * 8;
    const int arow = lane & 15, ac = lane >> 4;
    const int brow = o0 + (lane & 7), bc = (lane >> 3) & 1;
#pragma unroll
    for (int kc = 0; kc < 4; kc++) {
        u32 ao = swzT(arow, kc * 2 + ac);
        u32 bo = swzT(brow, kc * 2 + bc);
        u32 bh[2], bl[2], brh[2], brl[2];
        ldsm2(bh, sb + 16384 + bo);
        ldsm2(bl, sb + 24576 + bo);
        ldsm2(brh, sb + 32768 + bo);
        ldsm2(brl, sb + 40960 + bo);
        {
            u32 ach[4], acl[4], ash[4], asl[4];
            ldsm4(ach, sb + ao);
            ldsm4(acl, sb + 2048 + ao);
            ldsm4(ash, sb + 4096 + ao);
            ldsm4(asl, sb + 6144 + ao);
            mmabf(acc0, ach, bh);
            mmabf(acc0, ach, bl);
            mmabf(acc0, acl, bh);
            mmabf(acc0, ash, brh);
            mmabf(acc0, ash, brl);
            mmabf(acc0, asl, brh);
        }
        if (dual) {
            u32 ach[4], acl[4], ash[4], asl[4];
            ldsm4(ach, sb + 8192 + ao);
            ldsm4(acl, sb + 10240 + ao);
            ldsm4(ash, sb + 12288 + ao);
            ldsm4(asl, sb + 14336 + ao);
            mmabf(acc1, ach, brh);
            mmabf(acc1, ach, brl);
            mmabf(acc1, acl, brh);
            mmabf(acc1, ash, bh);
            mmabf(acc1, ash, bl);
            mmabf(acc1, asl, bh);
        }
    }
    // epilogue: coalesced stores to [tpos][img]
    const int g = lane >> 2, cp2 = (lane & 3) * 2;
    const int tpos0 = s2 * 64 + s1;
    const int tpos1 = f2 * 64 + f1;
#pragma unroll
    for (int half = 0; half < 2; half++) {
        int b = g + half * 8;
        bf16 h, l;
        bsplit(acc0[half * 2], h, l);
        g_Ttp[(size_t)tpos0 * 1024 + b * 64 + o0 + cp2] = pack_bf(h, l);
        bsplit(acc0[half * 2 + 1], h, l);
        g_Ttp[(size_t)tpos0 * 1024 + b * 64 + o0 + cp2 + 1] = pack_bf(h, l);
        if (dual) {
            bsplit(acc1[half * 2], h, l);
            g_Ttp[(size_t)tpos1 * 1024 + b * 64 + o0 + cp2] = pack_bf(h, l);
            bsplit(acc1[half * 2 + 1], h, l);
            g_Ttp[(size_t)tpos1 * 1024 + b * 64 + o0 + cp2 + 1] = pack_bf(h, l);
        }
    }
}

// ---------------- K45: fused inverse (per image) ----------------
__global__ __launch_bounds__(512, 1) void k45(const float* __restrict__ bias,
                                              float* __restrict__ out) {
    extern __shared__ char smem[];
    u32 sb = smem_u32(smem);
    const int PIPE = 131072, TT = 196608;
    int tid = threadIdx.x, lane = tid & 31, w = tid >> 5;
    int wy = w >> 1, wx = w & 1;
    int img = blockIdx.x;
    int g = lane >> 2, cp2 = (lane & 3) * 2;

    auto issueA = [&](int slot) {
        int cc = slot >> 1, k0 = (slot & 1) * 32;
        const bf16* Ah = g_A5h + cc * 16384;
        const bf16* Al = g_A5l + cc * 16384;
        u32 b = sb + PIPE + (slot & 1) * 32768;
#pragma unroll
        for (int t = 0; t < 2; t++) {
            int f = tid + t * 512, row = f >> 2, q = f & 3;
            cpa(b + SWZ(row, q), &Ah[row * 64 + k0 + q * 8]);
            cpa(b + 16384 + SWZ(row, q), &Al[row * 64 + k0 + q * 8]);
        }
        CPC();
    };
    issueA(0); issueA(1);

    // unpack packed Tot (coalesced [img][tpos]) into h/l swizzled tiles
#pragma unroll
    for (int t = 0; t < 8; t++) {
        int p = tid + t * 512;
        u32 v = g_Tt2[(size_t)img * 4096 + p];
        int r = p >> 6, cc = p & 63;
        u32 a = swzT(r, cc >> 3) + (cc & 7) * 2;
        *(unsigned short*)(smem + TT + a) = (unsigned short)(v & 0xFFFF);
        *(unsigned short*)(smem + TT + 8192 + a) = (unsigned short)(v >> 16);
    }

    int rA = wy * 32 + (lane & 15), cA = lane >> 4;
    int rB = wx * 32 + (lane & 7) + ((lane >> 4) << 3), cB = (lane >> 3) & 1;
    for (int cpass = 0; cpass < 2; cpass++) {
        float acc[2][4][4];
#pragma unroll
        for (int i = 0; i < 2; i++)
#pragma unroll
            for (int j = 0; j < 4; j++)
#pragma unroll
                for (int r = 0; r < 4; r++) acc[i][j][r] = 0.f;
        for (int k = 0; k < 2; k++) {
            int slot = cpass * 2 + k;
            if (slot < 3) { CPW1(); } else { CPW0(); }
            __syncthreads();
            u32 stg = sb + PIPE + (slot & 1) * 32768;
#pragma unroll
            for (int kk = 0; kk < 2; kk++) {
                u32 ah[2][4], al[2][4], bh[2][4], bl[2][4];
#pragma unroll
                for (int mi = 0; mi < 2; mi++) {
                    u32 ao = SWZ(rA + mi * 16, kk * 2 + cA);
                    ldsm4(ah[mi], stg + ao);
                    ldsm4(al[mi], stg + 16384 + ao);
                }
#pragma unroll
                for (int np = 0; np < 2; np++) {
                    int c16 = k * 4 + kk * 2 + cB;
                    u32 bo = swzT(rB + np * 16, c16);
                    ldsm4(bh[np], sb + TT + bo);
                    ldsm4(bl[np], sb + TT + 8192 + bo);
                }
#pragma unroll
                for (int mi = 0; mi < 2; mi++)
#pragma unroll
                    for (int ni = 0; ni < 4; ni++)
                        mmabf(acc[mi][ni], ah[mi], &bh[ni >> 1][(ni & 1) * 2]);
#pragma unroll
                for (int mi = 0; mi < 2; mi++)
#pragma unroll
                    for (int ni = 0; ni < 4; ni++)
                        mmabf(acc[mi][ni], ah[mi], &bl[ni >> 1][(ni & 1) * 2]);
#pragma unroll
                for (int mi = 0; mi < 2; mi++)
#pragma unroll
                    for (int ni = 0; ni < 4; ni++)
                        mmabf(acc[mi][ni], al[mi], &bh[ni >> 1][(ni & 1) * 2]);
            }
            __syncthreads();
            if (slot + 2 < 4) issueA(slot + 2);
        }
#pragma unroll
        for (int mi = 0; mi < 2; mi++)
#pragma unroll
            for (int ni = 0; ni < 4; ni++) {
                int col = cpass * 64 + wx * 32 + ni * 8 + cp2;
                int m0 = wy * 32 + mi * 16 + g;
                float* d = acc[mi][ni];
                u32 a0 = swzW(m0, col >> 3) + (col & 7) * 2;
                u32 a1 = swzW(m0 + 8, col >> 3) + (col & 7) * 2;
                *(u32*)(smem + a0) = pack_h(d[0], d[1]);
                *(u32*)(smem + 65536 + a0) = pack_l(d[0], d[1]);
                *(u32*)(smem + a1) = pack_h(d[2], d[3]);
                *(u32*)(smem + 65536 + a1) = pack_l(d[2], d[3]);
            }
    }
    __syncthreads();

    const float bv = bias[img & 63];
    const float sc = 1.0f / 65536.0f;
    int rB5 = wx * 64 + (lane & 7) + ((lane >> 4) << 3);
    for (int nh = 0; nh < 2; nh++) {
        float c5[2][8][4];
#pragma unroll
        for (int i = 0; i < 2; i++)
#pragma unroll
            for (int j = 0; j < 8; j++)
#pragma unroll
                for (int r = 0; r < 4; r++) c5[i][j][r] = 0.f;
        int xrow = tid >> 2, xq = tid & 3;
#pragma unroll
        for (int st = 0; st < 2; st++) {
            u32 b = sb + PIPE + st * 16384;
            cpa(b + SWZ(xrow, xq), &g_T5h[(nh * 128 + xrow) * 128 + st * 32 + xq * 8]);
            cpa(b + 8192 + SWZ(xrow, xq), &g_T5l[(nh * 128 + xrow) * 128 + st * 32 + xq * 8]);
            CPC();
        }
        for (int ch = 0; ch < 4; ch++) {
            if (ch < 3) { CPW1(); } else { CPW0(); }
            __syncthreads();
            if (ch + 2 < 4) {
                u32 b = sb + PIPE + ((ch + 2) % 3) * 16384;
                cpa(b + SWZ(xrow, xq), &g_T5h[(nh * 128 + xrow) * 128 + (ch + 2) * 32 + xq * 8]);
                cpa(b + 8192 + SWZ(xrow, xq), &g_T5l[(nh * 128 + xrow) * 128 + (ch + 2) * 32 + xq * 8]);
                CPC();
            }
            u32 stg = sb + PIPE + (ch % 3) * 16384;
#pragma unroll
            for (int kk = 0; kk < 2; kk++) {
                u32 ah[2][4], al[2][4], bh[4][4], bl[4][4];
#pragma unroll
                for (int mi = 0; mi < 2; mi++) {
                    int c16 = ch * 4 + kk * 2 + cA;
                    u32 ao = swzW(rA + mi * 16, c16);
                    ldsm4(ah[mi], sb + ao);
                    ldsm4(al[mi], sb + 65536 + ao);
                }
#pragma unroll
                for (int np = 0; np < 4; np++) {
                    u32 bo = SWZ(rB5 + np * 16, kk * 2 + cB);
                    ldsm4(bh[np], stg + bo);
                    ldsm4(bl[np], stg + 8192 + bo);
                }
#pragma unroll
                for (int mi = 0; mi < 2; mi++)
#pragma unroll
                    for (int ni = 0; ni < 8; ni++)
                        mmabf(c5[mi][ni], ah[mi], &bh[ni >> 1][(ni & 1) * 2]);
#pragma unroll
                for (int mi = 0; mi < 2; mi++)
#pragma unroll
                    for (int ni = 0; ni < 8; ni++)
                        mmabf(c5[mi][ni], ah[mi], &bl[ni >> 1][(ni & 1) * 2]);
#pragma unroll
                for (int mi = 0; mi < 2; mi++)
#pragma unroll
                    for (int ni = 0; ni < 8; ni++)
                        mmabf(c5[mi][ni], al[mi], &bh[ni >> 1][(ni & 1) * 2]);
            }
        }
#pragma unroll
        for (int mi = 0; mi < 2; mi++)
#pragma unroll
            for (int ni = 0; ni < 8; ni++) {
                int col = nh * 128 + wx * 64 + ni * 8 + cp2;
                float* d = c5[mi][ni];
#pragma unroll
                for (int half = 0; half < 2; half++) {
                    int m = wy * 32 + mi * 16 + g + half * 8;
                    float2 v;
                    v.x = fmaxf(fmaf(d[half * 2], sc, bv), 0.f);
                    v.y = fmaxf(fmaf(d[half * 2 + 1], sc, bv), 0.f);
                    *(float2*)&out[(size_t)img * 65536 + m * 256 + col] = v;
                }
            }
        __syncthreads();
    }
}

extern "C" void kernel_launch(void* const* d_in, const int* in_sizes, int n_in,
                              void* d_out, int out_size) {
    const float* x = (const float*)d_in[0];
    const float* wgt = (const float*)d_in[1];
    const float* bias = (const float*)d_in[2];
    float* out = (float*)d_out;

    static cudaStream_t side = nullptr;
    static cudaEvent_t evFork = nullptr, evJoin = nullptr;
    if (!side) {
        cudaStreamCreateWithFlags(&side, cudaStreamNonBlocking);
        cudaEventCreateWithFlags(&evFork, cudaEventDisableTiming);
        cudaEventCreateWithFlags(&evJoin, cudaEventDisableTiming);
    }
    cudaFuncSetAttribute(k12, cudaFuncAttributeMaxDynamicSharedMemorySize, 229376);
    cudaFuncSetAttribute(k45, cudaFuncAttributeMaxDynamicSharedMemorySize, 212992);

    cudaEventRecord(evFork, 0);
    cudaStreamWaitEvent(side, evFork, 0);
    k_wt<<<dim3(64, 64), 256, 0, side>>>(wgt);
    cudaEventRecord(evJoin, side);

    k_tables<<<256, 128>>>();
    k12<<<1024, 512, 229376>>>(x);

    cudaStreamWaitEvent(0, evJoin, 0);
    k_mix<<<4096, 256>>>();
    k_tt<<<dim3(32, 128), dim3(32, 8)>>>();
    k45<<<1024, 512, 212992>>>(bias, out);
}